// round 13
// baseline (speedup 1.0000x reference)
#include <cuda_runtime.h>
#include <math.h>

// ---------------------------------------------------------------------------
// Problem constants
// ---------------------------------------------------------------------------
#define N_NODES 50000
#define T_WIN   3
#define E_PER_T 100000
#define HID     128
#define NH      8
#define DK      16
#define M_ROWS  (T_WIN * N_NODES)          // 150000 rows
#define TN      (T_WIN * N_NODES)

// ---------------------------------------------------------------------------
// Device scratch
// ---------------------------------------------------------------------------
__device__ float g_q[(size_t)M_ROWS * HID];
__device__ float g_k[(size_t)M_ROWS * HID];
__device__ float g_v[(size_t)M_ROWS * HID];
__device__ float g_hc[(size_t)TN * HID];        // normalized causal + residual x
__device__ float g_hs[(size_t)TN * HID];        // normalized spurious
__device__ int   g_cnt[T_WIN * N_NODES];
__device__ int   g_off[T_WIN * (N_NODES + 1)];
__device__ int   g_csr[T_WIN * E_PER_T];

// ---------------------------------------------------------------------------
// Packed fp32x2 helpers
// ---------------------------------------------------------------------------
typedef unsigned long long u64;

__device__ __forceinline__ u64 fma2(u64 a, u64 b, u64 c) {
    u64 d;
    asm("fma.rn.f32x2 %0, %1, %2, %3;" : "=l"(d) : "l"(a), "l"(b), "l"(c));
    return d;
}
__device__ __forceinline__ u64 pack2(float lo, float hi) {
    u64 r;
    asm("mov.b64 %0, {%1, %2};" : "=l"(r) : "f"(lo), "f"(hi));
    return r;
}
__device__ __forceinline__ float2 unpack2(u64 v) {
    float2 f;
    asm("mov.b64 {%0, %1}, %2;" : "=f"(f.x), "=f"(f.y) : "l"(v));
    return f;
}

__device__ __forceinline__ void cp16(void* sdst, const void* gsrc) {
    unsigned sa = (unsigned)__cvta_generic_to_shared(sdst);
    asm volatile("cp.async.ca.shared.global [%0], [%1], 16;\n"
                 :: "r"(sa), "l"(gsrc) : "memory");
}
__device__ __forceinline__ void cp_commit() {
    asm volatile("cp.async.commit_group;\n" ::: "memory");
}

// ---------------------------------------------------------------------------
// CSR build: zero -> count -> scan -> fill
// ---------------------------------------------------------------------------
__global__ void zero_cnt_kernel() {
    int i = blockIdx.x * blockDim.x + threadIdx.x;
    if (i < T_WIN * N_NODES) g_cnt[i] = 0;
}

__global__ void count_kernel(const int* __restrict__ ei) {
    int g = blockIdx.x * blockDim.x + threadIdx.x;
    if (g >= T_WIN * E_PER_T) return;
    int t   = g / E_PER_T;
    int idx = g - t * E_PER_T;
    int tar = ei[(size_t)t * 2 * E_PER_T + E_PER_T + idx];
    atomicAdd(&g_cnt[t * N_NODES + tar], 1);
}

__global__ void __launch_bounds__(1024) scan_kernel() {
    const int t    = blockIdx.x;
    const int tid  = threadIdx.x;
    const int lane = tid & 31;
    const int wid  = tid >> 5;
    __shared__ int wsum[32];
    __shared__ int sbase;
    if (tid == 0) sbase = 0;
    __syncthreads();

    for (int c0 = 0; c0 < N_NODES; c0 += 1024) {
        int i = c0 + tid;
        int v = (i < N_NODES) ? g_cnt[t * N_NODES + i] : 0;
        int incl = v;
        #pragma unroll
        for (int o = 1; o < 32; o <<= 1) {
            int u = __shfl_up_sync(0xFFFFFFFFu, incl, o);
            if (lane >= o) incl += u;
        }
        if (lane == 31) wsum[wid] = incl;
        __syncthreads();
        if (wid == 0) {
            int wv = wsum[lane];
            #pragma unroll
            for (int o = 1; o < 32; o <<= 1) {
                int u = __shfl_up_sync(0xFFFFFFFFu, wv, o);
                if (lane >= o) wv += u;
            }
            wsum[lane] = wv;
        }
        __syncthreads();
        int excl = (wid > 0 ? wsum[wid - 1] : 0) + sbase + incl - v;
        if (i < N_NODES) {
            g_off[t * (N_NODES + 1) + i] = excl;
            g_cnt[t * N_NODES + i]       = excl;
        }
        __syncthreads();
        if (tid == 0) sbase += wsum[31];
        __syncthreads();
    }
    if (tid == 0) g_off[t * (N_NODES + 1) + N_NODES] = sbase;
}

__global__ void fill_kernel(const int* __restrict__ ei) {
    int g = blockIdx.x * blockDim.x + threadIdx.x;
    if (g >= T_WIN * E_PER_T) return;
    int t   = g / E_PER_T;
    int idx = g - t * E_PER_T;
    int src = ei[(size_t)t * 2 * E_PER_T + idx];
    int tar = ei[(size_t)t * 2 * E_PER_T + E_PER_T + idx];
    int pos = atomicAdd(&g_cnt[t * N_NODES + tar], 1);
    g_csr[(size_t)t * E_PER_T + pos] = src;
}

// ---------------------------------------------------------------------------
// K_qkv: BM=128, BN=128, BK=32, packed f32x2 (round-11 version)
// ---------------------------------------------------------------------------
__global__ void __launch_bounds__(256) qkv_kernel(
        const float* __restrict__ x,
        const float* __restrict__ Wq, const float* __restrict__ bq,
        const float* __restrict__ Wk, const float* __restrict__ bk,
        const float* __restrict__ Wv, const float* __restrict__ bv) {
    const float* W; const float* b; float* out;
    if (blockIdx.y == 0)      { W = Wq; b = bq; out = g_q; }
    else if (blockIdx.y == 1) { W = Wk; b = bk; out = g_k; }
    else                      { W = Wv; b = bv; out = g_v; }

    __shared__ float Xs[128][33];
    __shared__ float Ws[32][128];

    const int tid  = threadIdx.x;
    const int m0   = blockIdx.x * 128;
    const int ty   = tid >> 4;
    const int tx   = tid & 15;
    const int row0 = ty * 8;
    const int col0 = tx * 8;

    u64 acc[8][4];
    #pragma unroll
    for (int i = 0; i < 8; i++)
        #pragma unroll
        for (int j = 0; j < 4; j++) acc[i][j] = 0ull;

    for (int kc = 0; kc < 128; kc += 32) {
        #pragma unroll
        for (int l = 0; l < 4; l++) {
            int f4 = tid + l * 256;
            int r  = f4 >> 3;
            int c4 = f4 & 7;
            int grow = m0 + r;
            float4 val = make_float4(0.f, 0.f, 0.f, 0.f);
            if (grow < M_ROWS)
                val = *(const float4*)&x[(size_t)grow * HID + kc + c4 * 4];
            Xs[r][c4 * 4 + 0] = val.x;
            Xs[r][c4 * 4 + 1] = val.y;
            Xs[r][c4 * 4 + 2] = val.z;
            Xs[r][c4 * 4 + 3] = val.w;
        }
        #pragma unroll
        for (int l = 0; l < 4; l++) {
            int f4 = tid + l * 256;
            int r  = f4 >> 5;
            int c4 = f4 & 31;
            *(float4*)&Ws[r][c4 * 4] =
                *(const float4*)&W[(size_t)(kc + r) * HID + c4 * 4];
        }
        __syncthreads();

        #pragma unroll
        for (int k = 0; k < 32; k++) {
            ulonglong2 wb0 = *(const ulonglong2*)&Ws[k][col0];
            ulonglong2 wb1 = *(const ulonglong2*)&Ws[k][col0 + 4];
            #pragma unroll
            for (int i = 0; i < 8; i++) {
                u64 ap = pack2(Xs[row0 + i][k], Xs[row0 + i][k]);
                acc[i][0] = fma2(ap, wb0.x, acc[i][0]);
                acc[i][1] = fma2(ap, wb0.y, acc[i][1]);
                acc[i][2] = fma2(ap, wb1.x, acc[i][2]);
                acc[i][3] = fma2(ap, wb1.y, acc[i][3]);
            }
        }
        __syncthreads();
    }

    #pragma unroll
    for (int i = 0; i < 8; i++) {
        int grow = m0 + row0 + i;
        if (grow < M_ROWS) {
            float o[8];
            #pragma unroll
            for (int j = 0; j < 4; j++) {
                float2 v = unpack2(acc[i][j]);
                o[j * 2]     = v.x + b[col0 + j * 2];
                o[j * 2 + 1] = v.y + b[col0 + j * 2 + 1];
            }
            *(float4*)&out[(size_t)grow * HID + col0]     = make_float4(o[0], o[1], o[2], o[3]);
            *(float4*)&out[(size_t)grow * HID + col0 + 4] = make_float4(o[4], o[5], o[6], o[7]);
        }
    }
}

// ---------------------------------------------------------------------------
// K_agg (round-11): warp per NODE, k/v loaded once per (t_src, edge)
// ---------------------------------------------------------------------------
__global__ void __launch_bounds__(256) agg_kernel(const float* __restrict__ x) {
    const int warp = (blockIdx.x * blockDim.x + threadIdx.x) >> 5;
    const int lane = threadIdx.x & 31;
    if (warp >= N_NODES) return;
    const int n = warp;

    float4 q4[T_WIN];
    #pragma unroll
    for (int tt = 0; tt < T_WIN; tt++)
        q4[tt] = *(const float4*)&g_q[((size_t)tt * N_NODES + n) * HID + lane * 4];

    float ac[T_WIN][4], as[T_WIN][4], sc[T_WIN], ss[T_WIN];
    #pragma unroll
    for (int tt = 0; tt < T_WIN; tt++) {
        ac[tt][0] = ac[tt][1] = ac[tt][2] = ac[tt][3] = 0.f;
        as[tt][0] = as[tt][1] = as[tt][2] = as[tt][3] = 0.f;
        sc[tt] = 0.f; ss[tt] = 0.f;
    }

    #pragma unroll
    for (int ts = 0; ts < T_WIN; ts++) {
        const int s0 = g_off[ts * (N_NODES + 1) + n];
        const int s1 = g_off[ts * (N_NODES + 1) + n + 1];
        const int* csr = g_csr + (size_t)ts * E_PER_T;
        const float* kb = g_k + (size_t)ts * N_NODES * HID;
        const float* vb = g_v + (size_t)ts * N_NODES * HID;

        for (int e = s0; e < s1; e++) {
            int src = csr[e];
            size_t so = (size_t)src * HID + lane * 4;
            float4 k4 = *(const float4*)&kb[so];
            float4 v4 = *(const float4*)&vb[so];

            float d[T_WIN];
            #pragma unroll
            for (int tt = 0; tt < T_WIN; tt++) {
                if (tt < ts) continue;
                d[tt] = q4[tt].x * k4.x + q4[tt].y * k4.y
                      + q4[tt].z * k4.z + q4[tt].w * k4.w;
            }
            #pragma unroll
            for (int tt = 0; tt < T_WIN; tt++) {
                if (tt < ts) continue;
                d[tt] += __shfl_xor_sync(0xFFFFFFFFu, d[tt], 1);
            }
            #pragma unroll
            for (int tt = 0; tt < T_WIN; tt++) {
                if (tt < ts) continue;
                d[tt] += __shfl_xor_sync(0xFFFFFFFFu, d[tt], 2);
            }
            #pragma unroll
            for (int tt = 0; tt < T_WIN; tt++) {
                if (tt < ts) continue;
                float a  = d[tt] * 0.25f;
                float ec = expf(a);
                float es = expf(-a);
                sc[tt] += ec;  ss[tt] += es;
                ac[tt][0] = fmaf(ec, v4.x, ac[tt][0]);
                ac[tt][1] = fmaf(ec, v4.y, ac[tt][1]);
                ac[tt][2] = fmaf(ec, v4.z, ac[tt][2]);
                ac[tt][3] = fmaf(ec, v4.w, ac[tt][3]);
                as[tt][0] = fmaf(es, v4.x, as[tt][0]);
                as[tt][1] = fmaf(es, v4.y, as[tt][1]);
                as[tt][2] = fmaf(es, v4.z, as[tt][2]);
                as[tt][3] = fmaf(es, v4.w, as[tt][3]);
            }
        }
    }

    #pragma unroll
    for (int tt = 0; tt < T_WIN; tt++) {
        size_t rowoff = ((size_t)tt * N_NODES + n) * HID + lane * 4;
        const float ic = 1.0f / (sc[tt] + 1e-16f);
        const float is = 1.0f / (ss[tt] + 1e-16f);
        const float4 xv = *(const float4*)&x[rowoff];
        *(float4*)&g_hc[rowoff] = make_float4(
            fmaf(ac[tt][0], ic, xv.x), fmaf(ac[tt][1], ic, xv.y),
            fmaf(ac[tt][2], ic, xv.z), fmaf(ac[tt][3], ic, xv.w));
        *(float4*)&g_hs[rowoff] = make_float4(
            as[tt][0] * is, as[tt][1] * is, as[tt][2] * is, as[tt][3] * is);
    }
}

// ---------------------------------------------------------------------------
// K_ffn v10: BLOCK-COOPERATIVE. 256 threads, 32 instances (16 nodes x {c,s}).
// W read once per block (not per warp) -> crossbar redundancy /8.
// f32x2 packs two INSTANCES, so hn/g operands load pre-packed from
// transposed smem (hnT[k][inst], gT[j][inst], pad 36 -> conflict-free).
//  GEMM1: warp owns 32 cols, lane owns 4 cols x 8 inst (16 u64 accs).
//  GEMM2: warp owns 16 cols, lane owns 4 cols x 4 inst (8 u64 accs).
// W1/W2 staged via v5's cp.async double buffer (16 KB chunks).
// ---------------------------------------------------------------------------
#define HN_S 36
#define G_S  36
#define RB_S 132

__device__ __forceinline__ float gelu_exact(float v) {
    return 0.5f * v * (1.0f + erff(v * 0.70710678118654752f));
}

__global__ void __launch_bounds__(256, 2) ffn_kernel(
        const float* __restrict__ ln_s, const float* __restrict__ ln_b,
        const float* __restrict__ W1, const float* __restrict__ b1,
        const float* __restrict__ W2, const float* __restrict__ b2,
        float* __restrict__ out) {
    __shared__ __align__(16) float hnT[128 * HN_S];   // 18.4 KB (later rbuf)
    __shared__ __align__(16) float gT[256 * G_S];     // 36.9 KB
    __shared__ __align__(16) float ws[2][4096];       // 32 KB W stage (db)

    const int tid   = threadIdx.x;
    const int wib   = tid >> 5;
    const int lane  = tid & 31;
    const int nodeB = blockIdx.x * 16;                // grid = TN/16 exact

    // ---- kick off stage of W1 chunk 0 (16 rows x 256 = 16 KB)
    {
        const float4* g4 = (const float4*)W1;
        #pragma unroll
        for (int t = 0; t < 4; t++)
            cp16(&ws[0][(tid + t * 256) * 4], &g4[tid + t * 256]);
        cp_commit();
    }

    // ---- LN phase: warp wib handles instances wib*4 .. +4
    {
        const float4 lns = *(const float4*)&ln_s[lane * 4];
        const float4 lnb = *(const float4*)&ln_b[lane * 4];
        #pragma unroll
        for (int ii = 0; ii < 4; ii++) {
            int inst = wib * 4 + ii;
            int node = nodeB + (inst >> 1);
            size_t off = (size_t)node * HID + lane * 4;
            float4 h4 = (inst & 1) ? *(const float4*)&g_hs[off]
                                   : *(const float4*)&g_hc[off];
            float s1 = h4.x + h4.y + h4.z + h4.w;
            float s2 = h4.x*h4.x + h4.y*h4.y + h4.z*h4.z + h4.w*h4.w;
            #pragma unroll
            for (int o = 16; o > 0; o >>= 1) {
                s1 += __shfl_xor_sync(0xFFFFFFFFu, s1, o);
                s2 += __shfl_xor_sync(0xFFFFFFFFu, s2, o);
            }
            float mu   = s1 * (1.0f / 128.0f);
            float var  = s2 * (1.0f / 128.0f) - mu * mu;
            float rstd = rsqrtf(var + 1e-5f);
            // scatter into transposed hnT[k][inst]
            hnT[(lane * 4 + 0) * HN_S + inst] = (h4.x - mu) * rstd * lns.x + lnb.x;
            hnT[(lane * 4 + 1) * HN_S + inst] = (h4.y - mu) * rstd * lns.y + lnb.y;
            hnT[(lane * 4 + 2) * HN_S + inst] = (h4.z - mu) * rstd * lns.z + lnb.z;
            hnT[(lane * 4 + 3) * HN_S + inst] = (h4.w - mu) * rstd * lns.w + lnb.w;
        }
    }
    __syncthreads();

    // ---- GEMM1: C[32 inst x 256] = hn @ W1 + b1
    const int C0 = wib * 32 + (lane & 7) * 4;   // 4 cols
    const int IG = (lane >> 3) * 8;             // 8 instances (4 pairs)
    u64 a1[4][4];                               // [pair][col]
    {
        #pragma unroll
        for (int c = 0; c < 4; c++) {
            float bv = b1[C0 + c];
            u64 bp = pack2(bv, bv);
            #pragma unroll
            for (int p = 0; p < 4; p++) a1[p][c] = bp;
        }
    }
    #pragma unroll 1
    for (int c = 0; c < 8; c++) {
        if (c < 7) {
            const float4* g4 = (const float4*)(W1 + (size_t)(c + 1) * 16 * 256);
            #pragma unroll
            for (int t = 0; t < 4; t++)
                cp16(&ws[(c + 1) & 1][(tid + t * 256) * 4], &g4[tid + t * 256]);
            cp_commit();
            asm volatile("cp.async.wait_group 1;\n" ::: "memory");
        } else {
            asm volatile("cp.async.wait_group 0;\n" ::: "memory");
        }
        __syncthreads();

        const float* wsb = ws[c & 1];
        #pragma unroll 4
        for (int k = 0; k < 16; k++) {
            const int krow = c * 16 + k;
            ulonglong2 hA = *(const ulonglong2*)&hnT[krow * HN_S + IG];     // pairs 0,1
            ulonglong2 hB = *(const ulonglong2*)&hnT[krow * HN_S + IG + 4]; // pairs 2,3
            float w0 = wsb[k * 256 + C0];
            float w1 = wsb[k * 256 + C0 + 1];
            float w2 = wsb[k * 256 + C0 + 2];
            float w3 = wsb[k * 256 + C0 + 3];
            u64 wd0 = pack2(w0, w0), wd1 = pack2(w1, w1);
            u64 wd2 = pack2(w2, w2), wd3 = pack2(w3, w3);

            a1[0][0] = fma2(hA.x, wd0, a1[0][0]);
            a1[0][1] = fma2(hA.x, wd1, a1[0][1]);
            a1[0][2] = fma2(hA.x, wd2, a1[0][2]);
            a1[0][3] = fma2(hA.x, wd3, a1[0][3]);
            a1[1][0] = fma2(hA.y, wd0, a1[1][0]);
            a1[1][1] = fma2(hA.y, wd1, a1[1][1]);
            a1[1][2] = fma2(hA.y, wd2, a1[1][2]);
            a1[1][3] = fma2(hA.y, wd3, a1[1][3]);
            a1[2][0] = fma2(hB.x, wd0, a1[2][0]);
            a1[2][1] = fma2(hB.x, wd1, a1[2][1]);
            a1[2][2] = fma2(hB.x, wd2, a1[2][2]);
            a1[2][3] = fma2(hB.x, wd3, a1[2][3]);
            a1[3][0] = fma2(hB.y, wd0, a1[3][0]);
            a1[3][1] = fma2(hB.y, wd1, a1[3][1]);
            a1[3][2] = fma2(hB.y, wd2, a1[3][2]);
            a1[3][3] = fma2(hB.y, wd3, a1[3][3]);
        }
        __syncthreads();
    }

    // ---- kick off W2 chunk 0 (32 rows x 128 = 16 KB)
    {
        const float4* g4 = (const float4*)W2;
        #pragma unroll
        for (int t = 0; t < 4; t++)
            cp16(&ws[0][(tid + t * 256) * 4], &g4[tid + t * 256]);
        cp_commit();
    }

    // ---- GELU -> gT[col][inst] (pairs stored packed)
    #pragma unroll
    for (int p = 0; p < 4; p++) {
        #pragma unroll
        for (int c = 0; c < 4; c++) {
            float2 v = unpack2(a1[p][c]);
            u64 gw = pack2(gelu_exact(v.x), gelu_exact(v.y));
            *(u64*)&gT[(C0 + c) * G_S + IG + 2 * p] = gw;
        }
    }
    __syncthreads();

    // ---- GEMM2: C[32 inst x 128] = gelu(g) @ W2   (b2 added in epilogue)
    const int D0 = wib * 16 + (lane & 3) * 4;   // 4 cols
    const int IQ = (lane >> 2) * 4;             // 4 instances (2 pairs)
    u64 a2[2][4];
    #pragma unroll
    for (int p = 0; p < 2; p++)
        #pragma unroll
        for (int c = 0; c < 4; c++) a2[p][c] = 0ull;

    #pragma unroll 1
    for (int c2 = 0; c2 < 8; c2++) {
        if (c2 < 7) {
            const float4* g4 = (const float4*)(W2 + (size_t)(c2 + 1) * 32 * 128);
            #pragma unroll
            for (int t = 0; t < 4; t++)
                cp16(&ws[(c2 + 1) & 1][(tid + t * 256) * 4], &g4[tid + t * 256]);
            cp_commit();
            asm volatile("cp.async.wait_group 1;\n" ::: "memory");
        } else {
            asm volatile("cp.async.wait_group 0;\n" ::: "memory");
        }
        __syncthreads();

        const float* wsb = ws[c2 & 1];
        #pragma unroll 4
        for (int jj = 0; jj < 32; jj++) {
            const int j = c2 * 32 + jj;
            ulonglong2 gp = *(const ulonglong2*)&gT[j * G_S + IQ];
            float w0 = wsb[jj * 128 + D0];
            float w1 = wsb[jj * 128 + D0 + 1];
            float w2 = wsb[jj * 128 + D0 + 2];
            float w3 = wsb[jj * 128 + D0 + 3];
            u64 wd0 = pack2(w0, w0), wd1 = pack2(w1, w1);
            u64 wd2 = pack2(w2, w2), wd3 = pack2(w3, w3);

            a2[0][0] = fma2(gp.x, wd0, a2[0][0]);
            a2[0][1] = fma2(gp.x, wd1, a2[0][1]);
            a2[0][2] = fma2(gp.x, wd2, a2[0][2]);
            a2[0][3] = fma2(gp.x, wd3, a2[0][3]);
            a2[1][0] = fma2(gp.y, wd0, a2[1][0]);
            a2[1][1] = fma2(gp.y, wd1, a2[1][1]);
            a2[1][2] = fma2(gp.y, wd2, a2[1][2]);
            a2[1][3] = fma2(gp.y, wd3, a2[1][3]);
        }
        __syncthreads();
    }

    // ---- scatter r into rbuf (aliases hnT; all hnT readers done at GEMM1 end)
    float* rbuf = hnT;                           // [32 inst][RB_S]
    #pragma unroll
    for (int p = 0; p < 2; p++) {
        #pragma unroll
        for (int c = 0; c < 4; c++) {
            float2 v = unpack2(a2[p][c]);
            rbuf[(IQ + 2 * p)     * RB_S + D0 + c] = v.x;
            rbuf[(IQ + 2 * p + 1) * RB_S + D0 + c] = v.y;
        }
    }
    __syncthreads();

    // ---- epilogue: warp wib owns inst wib*4..+4 = nodes nodeB+wib*2, +1
    const size_t S = (size_t)TN * HID;
    const float4 b2v = *(const float4*)&b2[lane * 4];
    #pragma unroll
    for (int nn = 0; nn < 2; nn++) {
        int node = nodeB + wib * 2 + nn;
        size_t off = (size_t)node * HID + lane * 4;
        float4 hc4 = *(const float4*)&g_hc[off];
        float4 hs4 = *(const float4*)&g_hs[off];
        float4 rc4 = *(const float4*)&rbuf[(wib * 4 + 2 * nn)     * RB_S + lane * 4];
        float4 rs4 = *(const float4*)&rbuf[(wib * 4 + 2 * nn + 1) * RB_S + lane * 4];

        float oc[4] = { hc4.x + rc4.x + b2v.x, hc4.y + rc4.y + b2v.y,
                        hc4.z + rc4.z + b2v.z, hc4.w + rc4.w + b2v.w };
        float os[4] = { hs4.x + rs4.x + b2v.x, hs4.y + rs4.y + b2v.y,
                        hs4.z + rs4.z + b2v.z, hs4.w + rs4.w + b2v.w };

        *(float4*)&out[off]         = make_float4(oc[0]+os[0], oc[1]+os[1],
                                                  oc[2]+os[2], oc[3]+os[3]);
        *(float4*)&out[S + off]     = make_float4(oc[0], oc[1], oc[2], oc[3]);
        *(float4*)&out[2*S + off]   = make_float4(os[0], os[1], os[2], os[3]);
    }
}

// ---------------------------------------------------------------------------
// Launch
// ---------------------------------------------------------------------------
extern "C" void kernel_launch(void* const* d_in, const int* in_sizes, int n_in,
                              void* d_out, int out_size) {
    const float* x    = (const float*)d_in[0];
    const int*   ei   = (const int*)  d_in[1];
    const float* Wq   = (const float*)d_in[2];
    const float* bq   = (const float*)d_in[3];
    const float* Wk   = (const float*)d_in[4];
    const float* bk   = (const float*)d_in[5];
    const float* Wv   = (const float*)d_in[6];
    const float* bv   = (const float*)d_in[7];
    const float* ln_s = (const float*)d_in[8];
    const float* ln_b = (const float*)d_in[9];
    const float* W1   = (const float*)d_in[10];
    const float* b1   = (const float*)d_in[11];
    const float* W2   = (const float*)d_in[12];
    const float* b2   = (const float*)d_in[13];
    float* out = (float*)d_out;

    zero_cnt_kernel<<<(T_WIN * N_NODES + 255) / 256, 256>>>();
    count_kernel<<<(T_WIN * E_PER_T + 255) / 256, 256>>>(ei);
    scan_kernel<<<T_WIN, 1024>>>();
    fill_kernel<<<(T_WIN * E_PER_T + 255) / 256, 256>>>(ei);

    qkv_kernel<<<dim3((M_ROWS + 127) / 128, 3), 256>>>(x, Wq, bq, Wk, bk, Wv, bv);

    agg_kernel<<<(N_NODES * 32 + 255) / 256, 256>>>(x);

    // 16 nodes (32 instances) per block; TN/16 = 9375 exact
    ffn_kernel<<<TN / 16, 256>>>(ln_s, ln_b, W1, b1, W2, b2, out);
}

// round 14
// speedup vs baseline: 1.1216x; 1.1216x over previous
#include <cuda_runtime.h>
#include <math.h>

// ---------------------------------------------------------------------------
// Problem constants
// ---------------------------------------------------------------------------
#define N_NODES 50000
#define T_WIN   3
#define E_PER_T 100000
#define HID     128
#define NH      8
#define DK      16
#define M_ROWS  (T_WIN * N_NODES)          // 150000 rows
#define TN      (T_WIN * N_NODES)

// ---------------------------------------------------------------------------
// Device scratch
// ---------------------------------------------------------------------------
__device__ float g_q[(size_t)M_ROWS * HID];
__device__ float g_k[(size_t)M_ROWS * HID];
__device__ float g_v[(size_t)M_ROWS * HID];
__device__ float g_hc[(size_t)TN * HID];        // normalized causal + residual x
__device__ float g_hs[(size_t)TN * HID];        // normalized spurious
__device__ int   g_cnt[T_WIN * N_NODES];
__device__ int   g_off[T_WIN * (N_NODES + 1)];
__device__ int   g_csr[T_WIN * E_PER_T];

// ---------------------------------------------------------------------------
// Packed fp32x2 helpers
// ---------------------------------------------------------------------------
typedef unsigned long long u64;

__device__ __forceinline__ u64 fma2(u64 a, u64 b, u64 c) {
    u64 d;
    asm("fma.rn.f32x2 %0, %1, %2, %3;" : "=l"(d) : "l"(a), "l"(b), "l"(c));
    return d;
}
__device__ __forceinline__ u64 pack2(float lo, float hi) {
    u64 r;
    asm("mov.b64 %0, {%1, %2};" : "=l"(r) : "f"(lo), "f"(hi));
    return r;
}
__device__ __forceinline__ float2 unpack2(u64 v) {
    float2 f;
    asm("mov.b64 {%0, %1}, %2;" : "=f"(f.x), "=f"(f.y) : "l"(v));
    return f;
}

__device__ __forceinline__ void cp16(void* sdst, const void* gsrc) {
    unsigned sa = (unsigned)__cvta_generic_to_shared(sdst);
    asm volatile("cp.async.ca.shared.global [%0], [%1], 16;\n"
                 :: "r"(sa), "l"(gsrc) : "memory");
}
__device__ __forceinline__ void cp_commit() {
    asm volatile("cp.async.commit_group;\n" ::: "memory");
}

// ---------------------------------------------------------------------------
// CSR build: zero -> count -> scan -> fill
// ---------------------------------------------------------------------------
__global__ void zero_cnt_kernel() {
    int i = blockIdx.x * blockDim.x + threadIdx.x;
    if (i < T_WIN * N_NODES) g_cnt[i] = 0;
}

__global__ void count_kernel(const int* __restrict__ ei) {
    int g = blockIdx.x * blockDim.x + threadIdx.x;
    if (g >= T_WIN * E_PER_T) return;
    int t   = g / E_PER_T;
    int idx = g - t * E_PER_T;
    int tar = ei[(size_t)t * 2 * E_PER_T + E_PER_T + idx];
    atomicAdd(&g_cnt[t * N_NODES + tar], 1);
}

__global__ void __launch_bounds__(1024) scan_kernel() {
    const int t    = blockIdx.x;
    const int tid  = threadIdx.x;
    const int lane = tid & 31;
    const int wid  = tid >> 5;
    __shared__ int wsum[32];
    __shared__ int sbase;
    if (tid == 0) sbase = 0;
    __syncthreads();

    for (int c0 = 0; c0 < N_NODES; c0 += 1024) {
        int i = c0 + tid;
        int v = (i < N_NODES) ? g_cnt[t * N_NODES + i] : 0;
        int incl = v;
        #pragma unroll
        for (int o = 1; o < 32; o <<= 1) {
            int u = __shfl_up_sync(0xFFFFFFFFu, incl, o);
            if (lane >= o) incl += u;
        }
        if (lane == 31) wsum[wid] = incl;
        __syncthreads();
        if (wid == 0) {
            int wv = wsum[lane];
            #pragma unroll
            for (int o = 1; o < 32; o <<= 1) {
                int u = __shfl_up_sync(0xFFFFFFFFu, wv, o);
                if (lane >= o) wv += u;
            }
            wsum[lane] = wv;
        }
        __syncthreads();
        int excl = (wid > 0 ? wsum[wid - 1] : 0) + sbase + incl - v;
        if (i < N_NODES) {
            g_off[t * (N_NODES + 1) + i] = excl;
            g_cnt[t * N_NODES + i]       = excl;
        }
        __syncthreads();
        if (tid == 0) sbase += wsum[31];
        __syncthreads();
    }
    if (tid == 0) g_off[t * (N_NODES + 1) + N_NODES] = sbase;
}

__global__ void fill_kernel(const int* __restrict__ ei) {
    int g = blockIdx.x * blockDim.x + threadIdx.x;
    if (g >= T_WIN * E_PER_T) return;
    int t   = g / E_PER_T;
    int idx = g - t * E_PER_T;
    int src = ei[(size_t)t * 2 * E_PER_T + idx];
    int tar = ei[(size_t)t * 2 * E_PER_T + E_PER_T + idx];
    int pos = atomicAdd(&g_cnt[t * N_NODES + tar], 1);
    g_csr[(size_t)t * E_PER_T + pos] = src;
}

// ---------------------------------------------------------------------------
// K_qkv v3 (FUSED): one block per 128 rows computes q, k, AND v.
// X staged ONCE into smem (128x132, float4 stores); three passes stream
// their W tiles through a shared 32x128 staging buffer. Inner loop identical
// to round-11 (8 rows/thread, 4 packed cols, f32x2 math).
// ---------------------------------------------------------------------------
#define XS_S 132

__global__ void __launch_bounds__(256, 2) qkv_kernel(
        const float* __restrict__ x,
        const float* __restrict__ Wq, const float* __restrict__ bq,
        const float* __restrict__ Wk, const float* __restrict__ bk,
        const float* __restrict__ Wv, const float* __restrict__ bv) {
    __shared__ __align__(16) float Xs[128 * XS_S];   // 67.6 KB
    __shared__ float Ws[32][128];                    // 16 KB

    const int tid  = threadIdx.x;
    const int m0   = blockIdx.x * 128;
    const int ty   = tid >> 4;            // 0..15
    const int tx   = tid & 15;            // 0..15
    const int row0 = ty * 8;
    const int col0 = tx * 8;

    // ---- stage X tile 128x128 ONCE (16 float4 per thread)
    #pragma unroll
    for (int l = 0; l < 16; l++) {
        int f4 = tid + l * 256;           // 0..4095
        int r  = f4 >> 5;                 // 0..127
        int c4 = f4 & 31;                 // 0..31
        int grow = m0 + r;
        float4 val = make_float4(0.f, 0.f, 0.f, 0.f);
        if (grow < M_ROWS)
            val = *(const float4*)&x[(size_t)grow * HID + c4 * 4];
        *(float4*)&Xs[r * XS_S + c4 * 4] = val;
    }

    const float* Wm[3] = { Wq, Wk, Wv };
    const float* bm[3] = { bq, bk, bv };
    float* om[3];
    om[0] = g_q; om[1] = g_k; om[2] = g_v;

    #pragma unroll 1
    for (int m = 0; m < 3; m++) {
        const float* W = Wm[m];
        const float* b = bm[m];
        float* out = om[m];

        u64 acc[8][4];
        #pragma unroll
        for (int i = 0; i < 8; i++)
            #pragma unroll
            for (int j = 0; j < 4; j++) acc[i][j] = 0ull;

        #pragma unroll 1
        for (int kc = 0; kc < 128; kc += 32) {
            __syncthreads();              // Ws free (prev compute done / X staged)
            #pragma unroll
            for (int l = 0; l < 4; l++) {
                int f4 = tid + l * 256;
                int r  = f4 >> 5;
                int c4 = f4 & 31;
                *(float4*)&Ws[r][c4 * 4] =
                    *(const float4*)&W[(size_t)(kc + r) * HID + c4 * 4];
            }
            __syncthreads();

            #pragma unroll
            for (int k = 0; k < 32; k++) {
                ulonglong2 wb0 = *(const ulonglong2*)&Ws[k][col0];
                ulonglong2 wb1 = *(const ulonglong2*)&Ws[k][col0 + 4];
                #pragma unroll
                for (int i = 0; i < 8; i++) {
                    float xv = Xs[(row0 + i) * XS_S + kc + k];
                    u64 ap = pack2(xv, xv);
                    acc[i][0] = fma2(ap, wb0.x, acc[i][0]);
                    acc[i][1] = fma2(ap, wb0.y, acc[i][1]);
                    acc[i][2] = fma2(ap, wb1.x, acc[i][2]);
                    acc[i][3] = fma2(ap, wb1.y, acc[i][3]);
                }
            }
        }

        #pragma unroll
        for (int i = 0; i < 8; i++) {
            int grow = m0 + row0 + i;
            if (grow < M_ROWS) {
                float o[8];
                #pragma unroll
                for (int j = 0; j < 4; j++) {
                    float2 v = unpack2(acc[i][j]);
                    o[j * 2]     = v.x + b[col0 + j * 2];
                    o[j * 2 + 1] = v.y + b[col0 + j * 2 + 1];
                }
                *(float4*)&out[(size_t)grow * HID + col0]     = make_float4(o[0], o[1], o[2], o[3]);
                *(float4*)&out[(size_t)grow * HID + col0 + 4] = make_float4(o[4], o[5], o[6], o[7]);
            }
        }
    }
}

// ---------------------------------------------------------------------------
// K_agg (round-11): warp per NODE, k/v loaded once per (t_src, edge)
// ---------------------------------------------------------------------------
__global__ void __launch_bounds__(256) agg_kernel(const float* __restrict__ x) {
    const int warp = (blockIdx.x * blockDim.x + threadIdx.x) >> 5;
    const int lane = threadIdx.x & 31;
    if (warp >= N_NODES) return;
    const int n = warp;

    float4 q4[T_WIN];
    #pragma unroll
    for (int tt = 0; tt < T_WIN; tt++)
        q4[tt] = *(const float4*)&g_q[((size_t)tt * N_NODES + n) * HID + lane * 4];

    float ac[T_WIN][4], as[T_WIN][4], sc[T_WIN], ss[T_WIN];
    #pragma unroll
    for (int tt = 0; tt < T_WIN; tt++) {
        ac[tt][0] = ac[tt][1] = ac[tt][2] = ac[tt][3] = 0.f;
        as[tt][0] = as[tt][1] = as[tt][2] = as[tt][3] = 0.f;
        sc[tt] = 0.f; ss[tt] = 0.f;
    }

    #pragma unroll
    for (int ts = 0; ts < T_WIN; ts++) {
        const int s0 = g_off[ts * (N_NODES + 1) + n];
        const int s1 = g_off[ts * (N_NODES + 1) + n + 1];
        const int* csr = g_csr + (size_t)ts * E_PER_T;
        const float* kb = g_k + (size_t)ts * N_NODES * HID;
        const float* vb = g_v + (size_t)ts * N_NODES * HID;

        for (int e = s0; e < s1; e++) {
            int src = csr[e];
            size_t so = (size_t)src * HID + lane * 4;
            float4 k4 = *(const float4*)&kb[so];
            float4 v4 = *(const float4*)&vb[so];

            float d[T_WIN];
            #pragma unroll
            for (int tt = 0; tt < T_WIN; tt++) {
                if (tt < ts) continue;
                d[tt] = q4[tt].x * k4.x + q4[tt].y * k4.y
                      + q4[tt].z * k4.z + q4[tt].w * k4.w;
            }
            #pragma unroll
            for (int tt = 0; tt < T_WIN; tt++) {
                if (tt < ts) continue;
                d[tt] += __shfl_xor_sync(0xFFFFFFFFu, d[tt], 1);
            }
            #pragma unroll
            for (int tt = 0; tt < T_WIN; tt++) {
                if (tt < ts) continue;
                d[tt] += __shfl_xor_sync(0xFFFFFFFFu, d[tt], 2);
            }
            #pragma unroll
            for (int tt = 0; tt < T_WIN; tt++) {
                if (tt < ts) continue;
                float a  = d[tt] * 0.25f;
                float ec = expf(a);
                float es = expf(-a);
                sc[tt] += ec;  ss[tt] += es;
                ac[tt][0] = fmaf(ec, v4.x, ac[tt][0]);
                ac[tt][1] = fmaf(ec, v4.y, ac[tt][1]);
                ac[tt][2] = fmaf(ec, v4.z, ac[tt][2]);
                ac[tt][3] = fmaf(ec, v4.w, ac[tt][3]);
                as[tt][0] = fmaf(es, v4.x, as[tt][0]);
                as[tt][1] = fmaf(es, v4.y, as[tt][1]);
                as[tt][2] = fmaf(es, v4.z, as[tt][2]);
                as[tt][3] = fmaf(es, v4.w, as[tt][3]);
            }
        }
    }

    #pragma unroll
    for (int tt = 0; tt < T_WIN; tt++) {
        size_t rowoff = ((size_t)tt * N_NODES + n) * HID + lane * 4;
        const float ic = 1.0f / (sc[tt] + 1e-16f);
        const float is = 1.0f / (ss[tt] + 1e-16f);
        const float4 xv = *(const float4*)&x[rowoff];
        *(float4*)&g_hc[rowoff] = make_float4(
            fmaf(ac[tt][0], ic, xv.x), fmaf(ac[tt][1], ic, xv.y),
            fmaf(ac[tt][2], ic, xv.z), fmaf(ac[tt][3], ic, xv.w));
        *(float4*)&g_hs[rowoff] = make_float4(
            as[tt][0] * is, as[tt][1] * is, as[tt][2] * is, as[tt][3] * is);
    }
}

// ---------------------------------------------------------------------------
// K_ffn (round-6 v5, the empirical best): warp = 4 nodes (8 instances),
// f32x2 packed math, 2 blocks/SM. W1/W2 staged block-cooperatively via
// cp.async double buffer. Lane owns j-cols {lane*4..+4, 128+lane*4..+4}.
// ---------------------------------------------------------------------------
__device__ __forceinline__ float gelu_exact(float v) {
    return 0.5f * v * (1.0f + erff(v * 0.70710678118654752f));
}

__device__ __forceinline__ void ln_store4(float4 h4, int lane,
                                          float4 lns, float4 lnb,
                                          float* __restrict__ dst) {
    float s1 = h4.x + h4.y + h4.z + h4.w;
    float s2 = h4.x*h4.x + h4.y*h4.y + h4.z*h4.z + h4.w*h4.w;
    #pragma unroll
    for (int o = 16; o > 0; o >>= 1) {
        s1 += __shfl_xor_sync(0xFFFFFFFFu, s1, o);
        s2 += __shfl_xor_sync(0xFFFFFFFFu, s2, o);
    }
    float mu   = s1 * (1.0f / 128.0f);
    float var  = s2 * (1.0f / 128.0f) - mu * mu;
    float rstd = rsqrtf(var + 1e-5f);

    *(float4*)&dst[lane * 4] = make_float4(
        (h4.x - mu) * rstd * lns.x + lnb.x,
        (h4.y - mu) * rstd * lns.y + lnb.y,
        (h4.z - mu) * rstd * lns.z + lnb.z,
        (h4.w - mu) * rstd * lns.w + lnb.w);
}

__global__ void __launch_bounds__(256, 2) ffn_kernel(
        const float* __restrict__ ln_s, const float* __restrict__ ln_b,
        const float* __restrict__ W1, const float* __restrict__ b1,
        const float* __restrict__ W2, const float* __restrict__ b2,
        float* __restrict__ out) {
    __shared__ float sbuf[8][2048];                    // 64 KB per-warp hn/g
    __shared__ __align__(16) float ws[2][4096];        // 32 KB W stage (db)

    const int tid  = threadIdx.x;
    const int wib  = tid >> 5;
    const int lane = tid & 31;
    const int wg   = blockIdx.x * 8 + wib;     // warp id over TN/4 = 37500
    const bool active = (wg < TN / 4);

    float* hnf = sbuf[wib];
    float* gb  = sbuf[wib];

    const float4 lns = active ? *(const float4*)&ln_s[lane * 4] : make_float4(0,0,0,0);
    const float4 lnb = active ? *(const float4*)&ln_b[lane * 4] : make_float4(0,0,0,0);

    // ---- kick off stage of W1 chunk 0 (16 rows x 256 = 16 KB)
    {
        const float4* g4 = (const float4*)W1;
        #pragma unroll
        for (int t = 0; t < 4; t++)
            cp16(&ws[0][(tid + t * 256) * 4], &g4[tid + t * 256]);
        cp_commit();
    }

    // ---- phase 0: LayerNorm for 8 instances (f = nn*2 + {c,s})
    if (active) {
        #pragma unroll
        for (int nn = 0; nn < 4; nn++) {
            size_t off = ((size_t)wg * 4 + nn) * HID + lane * 4;
            float4 c4 = *(const float4*)&g_hc[off];
            float4 s4 = *(const float4*)&g_hs[off];
            ln_store4(c4, lane, lns, lnb, &hnf[(nn * 2 + 0) * 128]);
            ln_store4(s4, lane, lns, lnb, &hnf[(nn * 2 + 1) * 128]);
        }
    }
    __syncwarp();

    // ---- GEMM1: g[f][j] = sum_i hn[f][i]*W1[i][j] + b1[j]
    u64 a1[8][4];
    {
        ulonglong2 bA = *(const ulonglong2*)&b1[lane * 4];
        ulonglong2 bB = *(const ulonglong2*)&b1[128 + lane * 4];
        #pragma unroll
        for (int f = 0; f < 8; f++) {
            a1[f][0] = bA.x; a1[f][1] = bA.y; a1[f][2] = bB.x; a1[f][3] = bB.y;
        }
    }
    #pragma unroll 1
    for (int c = 0; c < 8; c++) {
        if (c < 7) {
            const float4* g4 = (const float4*)(W1 + (size_t)(c + 1) * 16 * 256);
            #pragma unroll
            for (int t = 0; t < 4; t++)
                cp16(&ws[(c + 1) & 1][(tid + t * 256) * 4], &g4[tid + t * 256]);
            cp_commit();
            asm volatile("cp.async.wait_group 1;\n" ::: "memory");
        } else {
            asm volatile("cp.async.wait_group 0;\n" ::: "memory");
        }
        __syncthreads();

        const float* wsb = ws[c & 1];
        #pragma unroll 1
        for (int ii = 0; ii < 16; ii += 2) {
            ulonglong2 wA0 = *(const ulonglong2*)&wsb[ii * 256 + lane * 4];
            ulonglong2 wB0 = *(const ulonglong2*)&wsb[ii * 256 + 128 + lane * 4];
            ulonglong2 wA1 = *(const ulonglong2*)&wsb[(ii + 1) * 256 + lane * 4];
            ulonglong2 wB1 = *(const ulonglong2*)&wsb[(ii + 1) * 256 + 128 + lane * 4];
            const int i = c * 16 + ii;

            #pragma unroll
            for (int f = 0; f < 8; f++) {
                float2 hv = *(const float2*)&hnf[f * 128 + i];
                u64 p0 = pack2(hv.x, hv.x);
                u64 p1 = pack2(hv.y, hv.y);
                a1[f][0] = fma2(p0, wA0.x, a1[f][0]);
                a1[f][1] = fma2(p0, wA0.y, a1[f][1]);
                a1[f][2] = fma2(p0, wB0.x, a1[f][2]);
                a1[f][3] = fma2(p0, wB0.y, a1[f][3]);
                a1[f][0] = fma2(p1, wA1.x, a1[f][0]);
                a1[f][1] = fma2(p1, wA1.y, a1[f][1]);
                a1[f][2] = fma2(p1, wB1.x, a1[f][2]);
                a1[f][3] = fma2(p1, wB1.y, a1[f][3]);
            }
        }
        __syncthreads();
    }

    // ---- kick off stage of W2 chunk 0 (32 rows x 128 = 16 KB)
    {
        const float4* g4 = (const float4*)W2;
        #pragma unroll
        for (int t = 0; t < 4; t++)
            cp16(&ws[0][(tid + t * 256) * 4], &g4[tid + t * 256]);
        cp_commit();
    }

    // ---- GELU, stage g to smem (logical cols lane*4 and 128+lane*4)
    #pragma unroll
    for (int f = 0; f < 8; f++) {
        float2 v0 = unpack2(a1[f][0]);
        float2 v1 = unpack2(a1[f][1]);
        float2 v2 = unpack2(a1[f][2]);
        float2 v3 = unpack2(a1[f][3]);
        *(float4*)&gb[f * 256 + lane * 4] =
            make_float4(gelu_exact(v0.x), gelu_exact(v0.y),
                        gelu_exact(v1.x), gelu_exact(v1.y));
        *(float4*)&gb[f * 256 + 128 + lane * 4] =
            make_float4(gelu_exact(v2.x), gelu_exact(v2.y),
                        gelu_exact(v3.x), gelu_exact(v3.y));
    }
    __syncwarp();

    // ---- GEMM2: r[f][d] = sum_j g[f][j]*W2[j][d] + b2[d], d = lane*4..+4
    u64 a2[8][2];
    {
        ulonglong2 bb = *(const ulonglong2*)&b2[lane * 4];
        #pragma unroll
        for (int f = 0; f < 8; f++) { a2[f][0] = bb.x; a2[f][1] = bb.y; }
    }
    #pragma unroll 1
    for (int c = 0; c < 8; c++) {
        if (c < 7) {
            const float4* g4 = (const float4*)(W2 + (size_t)(c + 1) * 32 * 128);
            #pragma unroll
            for (int t = 0; t < 4; t++)
                cp16(&ws[(c + 1) & 1][(tid + t * 256) * 4], &g4[tid + t * 256]);
            cp_commit();
            asm volatile("cp.async.wait_group 1;\n" ::: "memory");
        } else {
            asm volatile("cp.async.wait_group 0;\n" ::: "memory");
        }
        __syncthreads();

        const float* wsb = ws[c & 1];
        #pragma unroll 1
        for (int jj = 0; jj < 32; jj += 4) {
            ulonglong2 w0  = *(const ulonglong2*)&wsb[(jj + 0) * 128 + lane * 4];
            ulonglong2 w1  = *(const ulonglong2*)&wsb[(jj + 1) * 128 + lane * 4];
            ulonglong2 w2v = *(const ulonglong2*)&wsb[(jj + 2) * 128 + lane * 4];
            ulonglong2 w3v = *(const ulonglong2*)&wsb[(jj + 3) * 128 + lane * 4];
            const int j = c * 32 + jj;

            #pragma unroll
            for (int f = 0; f < 8; f++) {
                float4 gj = *(const float4*)&gb[f * 256 + j];
                u64 p0 = pack2(gj.x, gj.x);
                u64 p1 = pack2(gj.y, gj.y);
                u64 p2 = pack2(gj.z, gj.z);
                u64 p3 = pack2(gj.w, gj.w);
                a2[f][0] = fma2(p0, w0.x, a2[f][0]);
                a2[f][1] = fma2(p0, w0.y, a2[f][1]);
                a2[f][0] = fma2(p1, w1.x, a2[f][0]);
                a2[f][1] = fma2(p1, w1.y, a2[f][1]);
                a2[f][0] = fma2(p2, w2v.x, a2[f][0]);
                a2[f][1] = fma2(p2, w2v.y, a2[f][1]);
                a2[f][0] = fma2(p3, w3v.x, a2[f][0]);
                a2[f][1] = fma2(p3, w3v.y, a2[f][1]);
            }
        }
        __syncthreads();
    }

    if (!active) return;

    // ---- epilogue: residual (reload h, L2-hot), write xs/cs/ss
    const size_t S = (size_t)TN * HID;
    #pragma unroll
    for (int nn = 0; nn < 4; nn++) {
        size_t off = ((size_t)wg * 4 + nn) * HID + lane * 4;
        float4 c4 = *(const float4*)&g_hc[off];
        float4 s4 = *(const float4*)&g_hs[off];

        float2 c01 = unpack2(a2[nn * 2][0]);
        float2 c23 = unpack2(a2[nn * 2][1]);
        float2 s01 = unpack2(a2[nn * 2 + 1][0]);
        float2 s23 = unpack2(a2[nn * 2 + 1][1]);
        float oc[4] = { c4.x + c01.x, c4.y + c01.y, c4.z + c23.x, c4.w + c23.y };
        float os[4] = { s4.x + s01.x, s4.y + s01.y, s4.z + s23.x, s4.w + s23.y };

        *(float4*)&out[off]         = make_float4(oc[0]+os[0], oc[1]+os[1],
                                                  oc[2]+os[2], oc[3]+os[3]);
        *(float4*)&out[S + off]     = make_float4(oc[0], oc[1], oc[2], oc[3]);
        *(float4*)&out[2*S + off]   = make_float4(os[0], os[1], os[2], os[3]);
    }
}

// ---------------------------------------------------------------------------
// Launch
// ---------------------------------------------------------------------------
extern "C" void kernel_launch(void* const* d_in, const int* in_sizes, int n_in,
                              void* d_out, int out_size) {
    const float* x    = (const float*)d_in[0];
    const int*   ei   = (const int*)  d_in[1];
    const float* Wq   = (const float*)d_in[2];
    const float* bq   = (const float*)d_in[3];
    const float* Wk   = (const float*)d_in[4];
    const float* bk   = (const float*)d_in[5];
    const float* Wv   = (const float*)d_in[6];
    const float* bv   = (const float*)d_in[7];
    const float* ln_s = (const float*)d_in[8];
    const float* ln_b = (const float*)d_in[9];
    const float* W1   = (const float*)d_in[10];
    const float* b1   = (const float*)d_in[11];
    const float* W2   = (const float*)d_in[12];
    const float* b2   = (const float*)d_in[13];
    float* out = (float*)d_out;

    zero_cnt_kernel<<<(T_WIN * N_NODES + 255) / 256, 256>>>();
    count_kernel<<<(T_WIN * E_PER_T + 255) / 256, 256>>>(ei);
    scan_kernel<<<T_WIN, 1024>>>();
    fill_kernel<<<(T_WIN * E_PER_T + 255) / 256, 256>>>(ei);

    // Fused QKV: one block per 128 rows computes q, k, v
    qkv_kernel<<<(M_ROWS + 127) / 128, 256>>>(x, Wq, bq, Wk, bk, Wv, bv);

    agg_kernel<<<(N_NODES * 32 + 255) / 256, 256>>>(x);

    ffn_kernel<<<(TN / 4 + 7) / 8, 256>>>(ln_s, ln_b, W1, b1, W2, b2, out);
}

// round 15
// speedup vs baseline: 1.1343x; 1.0113x over previous
#include <cuda_runtime.h>
#include <math.h>

// ---------------------------------------------------------------------------
// Problem constants
// ---------------------------------------------------------------------------
#define N_NODES 50000
#define T_WIN   3
#define E_PER_T 100000
#define HID     128
#define NH      8
#define DK      16
#define M_ROWS  (T_WIN * N_NODES)          // 150000 rows
#define TN      (T_WIN * N_NODES)

// ---------------------------------------------------------------------------
// Device scratch
// ---------------------------------------------------------------------------
__device__ float g_q[(size_t)M_ROWS * HID];
__device__ float g_k[(size_t)M_ROWS * HID];
__device__ float g_v[(size_t)M_ROWS * HID];
__device__ float g_hc[(size_t)TN * HID];        // normalized causal + residual x
__device__ float g_hs[(size_t)TN * HID];        // normalized spurious
__device__ int   g_cnt[T_WIN * N_NODES];
__device__ int   g_off[T_WIN * (N_NODES + 1)];
__device__ int   g_csr[T_WIN * E_PER_T];

// ---------------------------------------------------------------------------
// Packed fp32x2 helpers
// ---------------------------------------------------------------------------
typedef unsigned long long u64;

__device__ __forceinline__ u64 fma2(u64 a, u64 b, u64 c) {
    u64 d;
    asm("fma.rn.f32x2 %0, %1, %2, %3;" : "=l"(d) : "l"(a), "l"(b), "l"(c));
    return d;
}
__device__ __forceinline__ u64 pack2(float lo, float hi) {
    u64 r;
    asm("mov.b64 %0, {%1, %2};" : "=l"(r) : "f"(lo), "f"(hi));
    return r;
}
__device__ __forceinline__ float2 unpack2(u64 v) {
    float2 f;
    asm("mov.b64 {%0, %1}, %2;" : "=f"(f.x), "=f"(f.y) : "l"(v));
    return f;
}

__device__ __forceinline__ void cp16(void* sdst, const void* gsrc) {
    unsigned sa = (unsigned)__cvta_generic_to_shared(sdst);
    asm volatile("cp.async.ca.shared.global [%0], [%1], 16;\n"
                 :: "r"(sa), "l"(gsrc) : "memory");
}
__device__ __forceinline__ void cp_commit() {
    asm volatile("cp.async.commit_group;\n" ::: "memory");
}

// ---------------------------------------------------------------------------
// CSR build: zero -> count -> scan -> fill
// ---------------------------------------------------------------------------
__global__ void zero_cnt_kernel() {
    int i = blockIdx.x * blockDim.x + threadIdx.x;
    if (i < T_WIN * N_NODES) g_cnt[i] = 0;
}

__global__ void count_kernel(const int* __restrict__ ei) {
    int g = blockIdx.x * blockDim.x + threadIdx.x;
    if (g >= T_WIN * E_PER_T) return;
    int t   = g / E_PER_T;
    int idx = g - t * E_PER_T;
    int tar = ei[(size_t)t * 2 * E_PER_T + E_PER_T + idx];
    atomicAdd(&g_cnt[t * N_NODES + tar], 1);
}

__global__ void __launch_bounds__(1024) scan_kernel() {
    const int t    = blockIdx.x;
    const int tid  = threadIdx.x;
    const int lane = tid & 31;
    const int wid  = tid >> 5;
    __shared__ int wsum[32];
    __shared__ int sbase;
    if (tid == 0) sbase = 0;
    __syncthreads();

    for (int c0 = 0; c0 < N_NODES; c0 += 1024) {
        int i = c0 + tid;
        int v = (i < N_NODES) ? g_cnt[t * N_NODES + i] : 0;
        int incl = v;
        #pragma unroll
        for (int o = 1; o < 32; o <<= 1) {
            int u = __shfl_up_sync(0xFFFFFFFFu, incl, o);
            if (lane >= o) incl += u;
        }
        if (lane == 31) wsum[wid] = incl;
        __syncthreads();
        if (wid == 0) {
            int wv = wsum[lane];
            #pragma unroll
            for (int o = 1; o < 32; o <<= 1) {
                int u = __shfl_up_sync(0xFFFFFFFFu, wv, o);
                if (lane >= o) wv += u;
            }
            wsum[lane] = wv;
        }
        __syncthreads();
        int excl = (wid > 0 ? wsum[wid - 1] : 0) + sbase + incl - v;
        if (i < N_NODES) {
            g_off[t * (N_NODES + 1) + i] = excl;
            g_cnt[t * N_NODES + i]       = excl;
        }
        __syncthreads();
        if (tid == 0) sbase += wsum[31];
        __syncthreads();
    }
    if (tid == 0) g_off[t * (N_NODES + 1) + N_NODES] = sbase;
}

__global__ void fill_kernel(const int* __restrict__ ei) {
    int g = blockIdx.x * blockDim.x + threadIdx.x;
    if (g >= T_WIN * E_PER_T) return;
    int t   = g / E_PER_T;
    int idx = g - t * E_PER_T;
    int src = ei[(size_t)t * 2 * E_PER_T + idx];
    int tar = ei[(size_t)t * 2 * E_PER_T + E_PER_T + idx];
    int pos = atomicAdd(&g_cnt[t * N_NODES + tar], 1);
    g_csr[(size_t)t * E_PER_T + pos] = src;
}

// ---------------------------------------------------------------------------
// K_qkv v4 (fused + cp.async double-buffered W staging).
// One block per 128 rows computes q, k, v. X staged once (128x132).
// 12 W chunks (3 matrices x 4 k-chunks) stream through ws[2] with
// prefetch-next-while-compute (the proven ffn staging pattern).
// ---------------------------------------------------------------------------
#define XS_S 132

__global__ void __launch_bounds__(256, 2) qkv_kernel(
        const float* __restrict__ x,
        const float* __restrict__ Wq, const float* __restrict__ bq,
        const float* __restrict__ Wk, const float* __restrict__ bk,
        const float* __restrict__ Wv, const float* __restrict__ bv) {
    __shared__ __align__(16) float Xs[128 * XS_S];   // 67.6 KB
    __shared__ __align__(16) float ws[2][4096];      // 32 KB W stage (db)

    const int tid  = threadIdx.x;
    const int m0   = blockIdx.x * 128;
    const int ty   = tid >> 4;            // 0..15
    const int tx   = tid & 15;            // 0..15
    const int row0 = ty * 8;
    const int col0 = tx * 8;

    const float* Wm[3] = { Wq, Wk, Wv };
    const float* bm[3] = { bq, bk, bv };
    float* om[3];
    om[0] = g_q; om[1] = g_k; om[2] = g_v;

    // ---- kick off stage of W chunk 0 (Wq rows 0..32)
    {
        const float4* g4 = (const float4*)Wq;
        #pragma unroll
        for (int t = 0; t < 4; t++)
            cp16(&ws[0][(tid + t * 256) * 4], &g4[tid + t * 256]);
        cp_commit();
    }

    // ---- stage X tile 128x128 ONCE (16 float4 per thread)
    #pragma unroll
    for (int l = 0; l < 16; l++) {
        int f4 = tid + l * 256;           // 0..4095
        int r  = f4 >> 5;                 // 0..127
        int c4 = f4 & 31;                 // 0..31
        int grow = m0 + r;
        float4 val = make_float4(0.f, 0.f, 0.f, 0.f);
        if (grow < M_ROWS)
            val = *(const float4*)&x[(size_t)grow * HID + c4 * 4];
        *(float4*)&Xs[r * XS_S + c4 * 4] = val;
    }

    u64 acc[8][4];
    #pragma unroll
    for (int i = 0; i < 8; i++)
        #pragma unroll
        for (int j = 0; j < 4; j++) acc[i][j] = 0ull;

    // ---- 12 chunks: chunk c -> matrix m = c>>2, kc = (c&3)*32
    #pragma unroll 1
    for (int c = 0; c < 12; c++) {
        // prefetch next chunk
        if (c < 11) {
            int cn = c + 1;
            const float* Wn = Wm[cn >> 2];
            const float4* g4 = (const float4*)(Wn + (size_t)(cn & 3) * 32 * HID);
            #pragma unroll
            for (int t = 0; t < 4; t++)
                cp16(&ws[(cn) & 1][(tid + t * 256) * 4], &g4[tid + t * 256]);
            cp_commit();
            asm volatile("cp.async.wait_group 1;\n" ::: "memory");
        } else {
            asm volatile("cp.async.wait_group 0;\n" ::: "memory");
        }
        __syncthreads();

        const float* wsb = ws[c & 1];
        const int kc = (c & 3) * 32;
        #pragma unroll
        for (int k = 0; k < 32; k++) {
            ulonglong2 wb0 = *(const ulonglong2*)&wsb[k * 128 + col0];
            ulonglong2 wb1 = *(const ulonglong2*)&wsb[k * 128 + col0 + 4];
            #pragma unroll
            for (int i = 0; i < 8; i++) {
                float xv = Xs[(row0 + i) * XS_S + kc + k];
                u64 ap = pack2(xv, xv);
                acc[i][0] = fma2(ap, wb0.x, acc[i][0]);
                acc[i][1] = fma2(ap, wb0.y, acc[i][1]);
                acc[i][2] = fma2(ap, wb1.x, acc[i][2]);
                acc[i][3] = fma2(ap, wb1.y, acc[i][3]);
            }
        }
        __syncthreads();

        // end of a matrix: write out, reset accumulators
        if ((c & 3) == 3) {
            const int m = c >> 2;
            const float* b = bm[m];
            float* outp = om[m];
            #pragma unroll
            for (int i = 0; i < 8; i++) {
                int grow = m0 + row0 + i;
                if (grow < M_ROWS) {
                    float o[8];
                    #pragma unroll
                    for (int j = 0; j < 4; j++) {
                        float2 v = unpack2(acc[i][j]);
                        o[j * 2]     = v.x + b[col0 + j * 2];
                        o[j * 2 + 1] = v.y + b[col0 + j * 2 + 1];
                    }
                    *(float4*)&outp[(size_t)grow * HID + col0]     = make_float4(o[0], o[1], o[2], o[3]);
                    *(float4*)&outp[(size_t)grow * HID + col0 + 4] = make_float4(o[4], o[5], o[6], o[7]);
                }
            }
            #pragma unroll
            for (int i = 0; i < 8; i++)
                #pragma unroll
                for (int j = 0; j < 4; j++) acc[i][j] = 0ull;
        }
    }
}

// ---------------------------------------------------------------------------
// K_agg (round-11): warp per NODE, k/v loaded once per (t_src, edge)
// ---------------------------------------------------------------------------
__global__ void __launch_bounds__(256) agg_kernel(const float* __restrict__ x) {
    const int warp = (blockIdx.x * blockDim.x + threadIdx.x) >> 5;
    const int lane = threadIdx.x & 31;
    if (warp >= N_NODES) return;
    const int n = warp;

    float4 q4[T_WIN];
    #pragma unroll
    for (int tt = 0; tt < T_WIN; tt++)
        q4[tt] = *(const float4*)&g_q[((size_t)tt * N_NODES + n) * HID + lane * 4];

    float ac[T_WIN][4], as[T_WIN][4], sc[T_WIN], ss[T_WIN];
    #pragma unroll
    for (int tt = 0; tt < T_WIN; tt++) {
        ac[tt][0] = ac[tt][1] = ac[tt][2] = ac[tt][3] = 0.f;
        as[tt][0] = as[tt][1] = as[tt][2] = as[tt][3] = 0.f;
        sc[tt] = 0.f; ss[tt] = 0.f;
    }

    #pragma unroll
    for (int ts = 0; ts < T_WIN; ts++) {
        const int s0 = g_off[ts * (N_NODES + 1) + n];
        const int s1 = g_off[ts * (N_NODES + 1) + n + 1];
        const int* csr = g_csr + (size_t)ts * E_PER_T;
        const float* kb = g_k + (size_t)ts * N_NODES * HID;
        const float* vb = g_v + (size_t)ts * N_NODES * HID;

        for (int e = s0; e < s1; e++) {
            int src = csr[e];
            size_t so = (size_t)src * HID + lane * 4;
            float4 k4 = *(const float4*)&kb[so];
            float4 v4 = *(const float4*)&vb[so];

            float d[T_WIN];
            #pragma unroll
            for (int tt = 0; tt < T_WIN; tt++) {
                if (tt < ts) continue;
                d[tt] = q4[tt].x * k4.x + q4[tt].y * k4.y
                      + q4[tt].z * k4.z + q4[tt].w * k4.w;
            }
            #pragma unroll
            for (int tt = 0; tt < T_WIN; tt++) {
                if (tt < ts) continue;
                d[tt] += __shfl_xor_sync(0xFFFFFFFFu, d[tt], 1);
            }
            #pragma unroll
            for (int tt = 0; tt < T_WIN; tt++) {
                if (tt < ts) continue;
                d[tt] += __shfl_xor_sync(0xFFFFFFFFu, d[tt], 2);
            }
            #pragma unroll
            for (int tt = 0; tt < T_WIN; tt++) {
                if (tt < ts) continue;
                float a  = d[tt] * 0.25f;
                float ec = expf(a);
                float es = expf(-a);
                sc[tt] += ec;  ss[tt] += es;
                ac[tt][0] = fmaf(ec, v4.x, ac[tt][0]);
                ac[tt][1] = fmaf(ec, v4.y, ac[tt][1]);
                ac[tt][2] = fmaf(ec, v4.z, ac[tt][2]);
                ac[tt][3] = fmaf(ec, v4.w, ac[tt][3]);
                as[tt][0] = fmaf(es, v4.x, as[tt][0]);
                as[tt][1] = fmaf(es, v4.y, as[tt][1]);
                as[tt][2] = fmaf(es, v4.z, as[tt][2]);
                as[tt][3] = fmaf(es, v4.w, as[tt][3]);
            }
        }
    }

    #pragma unroll
    for (int tt = 0; tt < T_WIN; tt++) {
        size_t rowoff = ((size_t)tt * N_NODES + n) * HID + lane * 4;
        const float ic = 1.0f / (sc[tt] + 1e-16f);
        const float is = 1.0f / (ss[tt] + 1e-16f);
        const float4 xv = *(const float4*)&x[rowoff];
        *(float4*)&g_hc[rowoff] = make_float4(
            fmaf(ac[tt][0], ic, xv.x), fmaf(ac[tt][1], ic, xv.y),
            fmaf(ac[tt][2], ic, xv.z), fmaf(ac[tt][3], ic, xv.w));
        *(float4*)&g_hs[rowoff] = make_float4(
            as[tt][0] * is, as[tt][1] * is, as[tt][2] * is, as[tt][3] * is);
    }
}

// ---------------------------------------------------------------------------
// K_ffn (round-6 v5, the empirical best): warp = 4 nodes (8 instances),
// f32x2 packed math, 2 blocks/SM. W1/W2 staged block-cooperatively via
// cp.async double buffer. Lane owns j-cols {lane*4..+4, 128+lane*4..+4}.
// ---------------------------------------------------------------------------
__device__ __forceinline__ float gelu_exact(float v) {
    return 0.5f * v * (1.0f + erff(v * 0.70710678118654752f));
}

__device__ __forceinline__ void ln_store4(float4 h4, int lane,
                                          float4 lns, float4 lnb,
                                          float* __restrict__ dst) {
    float s1 = h4.x + h4.y + h4.z + h4.w;
    float s2 = h4.x*h4.x + h4.y*h4.y + h4.z*h4.z + h4.w*h4.w;
    #pragma unroll
    for (int o = 16; o > 0; o >>= 1) {
        s1 += __shfl_xor_sync(0xFFFFFFFFu, s1, o);
        s2 += __shfl_xor_sync(0xFFFFFFFFu, s2, o);
    }
    float mu   = s1 * (1.0f / 128.0f);
    float var  = s2 * (1.0f / 128.0f) - mu * mu;
    float rstd = rsqrtf(var + 1e-5f);

    *(float4*)&dst[lane * 4] = make_float4(
        (h4.x - mu) * rstd * lns.x + lnb.x,
        (h4.y - mu) * rstd * lns.y + lnb.y,
        (h4.z - mu) * rstd * lns.z + lnb.z,
        (h4.w - mu) * rstd * lns.w + lnb.w);
}

__global__ void __launch_bounds__(256, 2) ffn_kernel(
        const float* __restrict__ ln_s, const float* __restrict__ ln_b,
        const float* __restrict__ W1, const float* __restrict__ b1,
        const float* __restrict__ W2, const float* __restrict__ b2,
        float* __restrict__ out) {
    __shared__ float sbuf[8][2048];                    // 64 KB per-warp hn/g
    __shared__ __align__(16) float ws[2][4096];        // 32 KB W stage (db)

    const int tid  = threadIdx.x;
    const int wib  = tid >> 5;
    const int lane = tid & 31;
    const int wg   = blockIdx.x * 8 + wib;     // warp id over TN/4 = 37500
    const bool active = (wg < TN / 4);

    float* hnf = sbuf[wib];
    float* gb  = sbuf[wib];

    const float4 lns = active ? *(const float4*)&ln_s[lane * 4] : make_float4(0,0,0,0);
    const float4 lnb = active ? *(const float4*)&ln_b[lane * 4] : make_float4(0,0,0,0);

    // ---- kick off stage of W1 chunk 0 (16 rows x 256 = 16 KB)
    {
        const float4* g4 = (const float4*)W1;
        #pragma unroll
        for (int t = 0; t < 4; t++)
            cp16(&ws[0][(tid + t * 256) * 4], &g4[tid + t * 256]);
        cp_commit();
    }

    // ---- phase 0: LayerNorm for 8 instances (f = nn*2 + {c,s})
    if (active) {
        #pragma unroll
        for (int nn = 0; nn < 4; nn++) {
            size_t off = ((size_t)wg * 4 + nn) * HID + lane * 4;
            float4 c4 = *(const float4*)&g_hc[off];
            float4 s4 = *(const float4*)&g_hs[off];
            ln_store4(c4, lane, lns, lnb, &hnf[(nn * 2 + 0) * 128]);
            ln_store4(s4, lane, lns, lnb, &hnf[(nn * 2 + 1) * 128]);
        }
    }
    __syncwarp();

    // ---- GEMM1: g[f][j] = sum_i hn[f][i]*W1[i][j] + b1[j]
    u64 a1[8][4];
    {
        ulonglong2 bA = *(const ulonglong2*)&b1[lane * 4];
        ulonglong2 bB = *(const ulonglong2*)&b1[128 + lane * 4];
        #pragma unroll
        for (int f = 0; f < 8; f++) {
            a1[f][0] = bA.x; a1[f][1] = bA.y; a1[f][2] = bB.x; a1[f][3] = bB.y;
        }
    }
    #pragma unroll 1
    for (int c = 0; c < 8; c++) {
        if (c < 7) {
            const float4* g4 = (const float4*)(W1 + (size_t)(c + 1) * 16 * 256);
            #pragma unroll
            for (int t = 0; t < 4; t++)
                cp16(&ws[(c + 1) & 1][(tid + t * 256) * 4], &g4[tid + t * 256]);
            cp_commit();
            asm volatile("cp.async.wait_group 1;\n" ::: "memory");
        } else {
            asm volatile("cp.async.wait_group 0;\n" ::: "memory");
        }
        __syncthreads();

        const float* wsb = ws[c & 1];
        #pragma unroll 1
        for (int ii = 0; ii < 16; ii += 2) {
            ulonglong2 wA0 = *(const ulonglong2*)&wsb[ii * 256 + lane * 4];
            ulonglong2 wB0 = *(const ulonglong2*)&wsb[ii * 256 + 128 + lane * 4];
            ulonglong2 wA1 = *(const ulonglong2*)&wsb[(ii + 1) * 256 + lane * 4];
            ulonglong2 wB1 = *(const ulonglong2*)&wsb[(ii + 1) * 256 + 128 + lane * 4];
            const int i = c * 16 + ii;

            #pragma unroll
            for (int f = 0; f < 8; f++) {
                float2 hv = *(const float2*)&hnf[f * 128 + i];
                u64 p0 = pack2(hv.x, hv.x);
                u64 p1 = pack2(hv.y, hv.y);
                a1[f][0] = fma2(p0, wA0.x, a1[f][0]);
                a1[f][1] = fma2(p0, wA0.y, a1[f][1]);
                a1[f][2] = fma2(p0, wB0.x, a1[f][2]);
                a1[f][3] = fma2(p0, wB0.y, a1[f][3]);
                a1[f][0] = fma2(p1, wA1.x, a1[f][0]);
                a1[f][1] = fma2(p1, wA1.y, a1[f][1]);
                a1[f][2] = fma2(p1, wB1.x, a1[f][2]);
                a1[f][3] = fma2(p1, wB1.y, a1[f][3]);
            }
        }
        __syncthreads();
    }

    // ---- kick off stage of W2 chunk 0 (32 rows x 128 = 16 KB)
    {
        const float4* g4 = (const float4*)W2;
        #pragma unroll
        for (int t = 0; t < 4; t++)
            cp16(&ws[0][(tid + t * 256) * 4], &g4[tid + t * 256]);
        cp_commit();
    }

    // ---- GELU, stage g to smem (logical cols lane*4 and 128+lane*4)
    #pragma unroll
    for (int f = 0; f < 8; f++) {
        float2 v0 = unpack2(a1[f][0]);
        float2 v1 = unpack2(a1[f][1]);
        float2 v2 = unpack2(a1[f][2]);
        float2 v3 = unpack2(a1[f][3]);
        *(float4*)&gb[f * 256 + lane * 4] =
            make_float4(gelu_exact(v0.x), gelu_exact(v0.y),
                        gelu_exact(v1.x), gelu_exact(v1.y));
        *(float4*)&gb[f * 256 + 128 + lane * 4] =
            make_float4(gelu_exact(v2.x), gelu_exact(v2.y),
                        gelu_exact(v3.x), gelu_exact(v3.y));
    }
    __syncwarp();

    // ---- GEMM2: r[f][d] = sum_j g[f][j]*W2[j][d] + b2[d], d = lane*4..+4
    u64 a2[8][2];
    {
        ulonglong2 bb = *(const ulonglong2*)&b2[lane * 4];
        #pragma unroll
        for (int f = 0; f < 8; f++) { a2[f][0] = bb.x; a2[f][1] = bb.y; }
    }
    #pragma unroll 1
    for (int c = 0; c < 8; c++) {
        if (c < 7) {
            const float4* g4 = (const float4*)(W2 + (size_t)(c + 1) * 32 * 128);
            #pragma unroll
            for (int t = 0; t < 4; t++)
                cp16(&ws[(c + 1) & 1][(tid + t * 256) * 4], &g4[tid + t * 256]);
            cp_commit();
            asm volatile("cp.async.wait_group 1;\n" ::: "memory");
        } else {
            asm volatile("cp.async.wait_group 0;\n" ::: "memory");
        }
        __syncthreads();

        const float* wsb = ws[c & 1];
        #pragma unroll 1
        for (int jj = 0; jj < 32; jj += 4) {
            ulonglong2 w0  = *(const ulonglong2*)&wsb[(jj + 0) * 128 + lane * 4];
            ulonglong2 w1  = *(const ulonglong2*)&wsb[(jj + 1) * 128 + lane * 4];
            ulonglong2 w2v = *(const ulonglong2*)&wsb[(jj + 2) * 128 + lane * 4];
            ulonglong2 w3v = *(const ulonglong2*)&wsb[(jj + 3) * 128 + lane * 4];
            const int j = c * 32 + jj;

            #pragma unroll
            for (int f = 0; f < 8; f++) {
                float4 gj = *(const float4*)&gb[f * 256 + j];
                u64 p0 = pack2(gj.x, gj.x);
                u64 p1 = pack2(gj.y, gj.y);
                u64 p2 = pack2(gj.z, gj.z);
                u64 p3 = pack2(gj.w, gj.w);
                a2[f][0] = fma2(p0, w0.x, a2[f][0]);
                a2[f][1] = fma2(p0, w0.y, a2[f][1]);
                a2[f][0] = fma2(p1, w1.x, a2[f][0]);
                a2[f][1] = fma2(p1, w1.y, a2[f][1]);
                a2[f][0] = fma2(p2, w2v.x, a2[f][0]);
                a2[f][1] = fma2(p2, w2v.y, a2[f][1]);
                a2[f][0] = fma2(p3, w3v.x, a2[f][0]);
                a2[f][1] = fma2(p3, w3v.y, a2[f][1]);
            }
        }
        __syncthreads();
    }

    if (!active) return;

    // ---- epilogue: residual (reload h, L2-hot), write xs/cs/ss
    const size_t S = (size_t)TN * HID;
    #pragma unroll
    for (int nn = 0; nn < 4; nn++) {
        size_t off = ((size_t)wg * 4 + nn) * HID + lane * 4;
        float4 c4 = *(const float4*)&g_hc[off];
        float4 s4 = *(const float4*)&g_hs[off];

        float2 c01 = unpack2(a2[nn * 2][0]);
        float2 c23 = unpack2(a2[nn * 2][1]);
        float2 s01 = unpack2(a2[nn * 2 + 1][0]);
        float2 s23 = unpack2(a2[nn * 2 + 1][1]);
        float oc[4] = { c4.x + c01.x, c4.y + c01.y, c4.z + c23.x, c4.w + c23.y };
        float os[4] = { s4.x + s01.x, s4.y + s01.y, s4.z + s23.x, s4.w + s23.y };

        *(float4*)&out[off]         = make_float4(oc[0]+os[0], oc[1]+os[1],
                                                  oc[2]+os[2], oc[3]+os[3]);
        *(float4*)&out[S + off]     = make_float4(oc[0], oc[1], oc[2], oc[3]);
        *(float4*)&out[2*S + off]   = make_float4(os[0], os[1], os[2], os[3]);
    }
}

// ---------------------------------------------------------------------------
// Launch
// ---------------------------------------------------------------------------
extern "C" void kernel_launch(void* const* d_in, const int* in_sizes, int n_in,
                              void* d_out, int out_size) {
    const float* x    = (const float*)d_in[0];
    const int*   ei   = (const int*)  d_in[1];
    const float* Wq   = (const float*)d_in[2];
    const float* bq   = (const float*)d_in[3];
    const float* Wk   = (const float*)d_in[4];
    const float* bk   = (const float*)d_in[5];
    const float* Wv   = (const float*)d_in[6];
    const float* bv   = (const float*)d_in[7];
    const float* ln_s = (const float*)d_in[8];
    const float* ln_b = (const float*)d_in[9];
    const float* W1   = (const float*)d_in[10];
    const float* b1   = (const float*)d_in[11];
    const float* W2   = (const float*)d_in[12];
    const float* b2   = (const float*)d_in[13];
    float* out = (float*)d_out;

    zero_cnt_kernel<<<(T_WIN * N_NODES + 255) / 256, 256>>>();
    count_kernel<<<(T_WIN * E_PER_T + 255) / 256, 256>>>(ei);
    scan_kernel<<<T_WIN, 1024>>>();
    fill_kernel<<<(T_WIN * E_PER_T + 255) / 256, 256>>>(ei);

    // Fused QKV with cp.async double-buffered W staging
    qkv_kernel<<<(M_ROWS + 127) / 128, 256>>>(x, Wq, bq, Wk, bk, Wv, bv);

    agg_kernel<<<(N_NODES * 32 + 255) / 256, 256>>>(x);

    ffn_kernel<<<(TN / 4 + 7) / 8, 256>>>(ln_s, ln_b, W1, b1, W2, b2, out);
}